// round 3
// baseline (speedup 1.0000x reference)
#include <cuda_runtime.h>

#define BATCH 8
#define LBL 8
#define EDIM 4
#define HT 640
#define WD 640
#define HW (HT*WD)
#define NV4 (HW/4)
#define NTHR 256
#define WARPS 8
#define PB 37                       // blocks per image
#define NBLK (PB*BATCH)             // 296 = 2 per SM on 148 SMs
#define STRIDE (PB*NTHR)            // 9472
#define ITERS 11                    // ceil(NV4/STRIDE)
#define DIAG 905.0966799187808f

typedef unsigned long long u64;
typedef unsigned int u32;

// ---------- global scratch: ALL zero at rest (module load / post-finalize) ----------
__device__ u64   g_occ [BATCH][LBL];     // packed (max_key<<32)|second_key, key=~idx, 0=empty
__device__ float g_sumk[BATCH][LBL][EDIM];
__device__ float g_cntk[BATCH][LBL];
__device__ float g_agg [BATCH][LBL];
__device__ float g_cntf[BATCH][LBL];
__device__ float g_dr  [BATCH];          // rewritten each replay before read
__device__ u32   g_c1, g_c2;

// keep the two LARGEST keys (= two smallest pixel indices) at *p
__device__ __forceinline__ void merge_max2(u64* p, u32 k){
  u64 old = *p;
  for(;;){
    u32 g1 = (u32)(old>>32), g2 = (u32)old;
    if (k <= g2) return;
    u32 m1, m2;
    if (k > g1){ m1 = k; m2 = g1; } else { m1 = g1; m2 = k; }
    u64 nv = ((u64)m1<<32) | (u64)m2;
    u64 prev = atomicCAS(p, old, nv);
    if (prev == old) return;
    old = prev;
  }
}

__global__ void __launch_bounds__(NTHR, 2) kAll(const float* __restrict__ emb,
                                                const int*   __restrict__ inst,
                                                const float* __restrict__ kern,
                                                const float* __restrict__ tmask,
                                                float* __restrict__ out){
  const int b    = blockIdx.y;
  const int x    = blockIdx.x;
  const int tid  = threadIdx.x;
  const int w    = tid >> 5;
  const int lane = tid & 31;

  __shared__ float s_buf [WARPS][LBL][EDIM][32];  // 32 KB: phase A sums, phase D vals (alias)
  __shared__ float s_cnt2[WARPS][LBL][32];        //  8 KB: phase A cntk, phase D cnt
  __shared__ u64   s_occ[LBL];
  __shared__ float sm[LBL][5];
  __shared__ float scd[LBL], sss[LBL], sst[LBL];
  __shared__ float red[64];
  __shared__ int   s_last;

  // ---------------- phase A init ----------------
  for (int i = tid; i < WARPS*LBL*EDIM*32; i += NTHR) ((float*)s_buf )[i] = 0.f;
  for (int i = tid; i < WARPS*LBL*32;      i += NTHR) ((float*)s_cnt2)[i] = 0.f;
  if (tid < LBL) s_occ[tid] = 0ull;
  __syncthreads();

  const float*  eb = emb + (size_t)b*EDIM*HW;
  const int4*   ip = (const int4*)  (inst  + (size_t)b*HW);
  const float4* kp = (const float4*)(kern  + (size_t)b*HW);
  const float4* tp = (const float4*)(tmask + (size_t)b*HW);

  float* mysum = &s_buf [w][0][0][lane];   // + l*128 + d*32
  float* mycnt = &s_cnt2[w][0][lane];      // + l*32
  u32 labpk[ITERS];

  // ---------------- phase A: occurrences + kernel-region sums + label cache --
  #pragma unroll
  for (int it = 0; it < ITERS; it++){
    int i = x*NTHR + tid + it*STRIDE;
    u32 pk = 0;
    if (i < NV4){
      int4   iv = ip[i];
      float4 kv = kp[i];
      float4 tv = tp[i];
      float4 e0 = ((const float4*)(eb       ))[i];
      float4 e1 = ((const float4*)(eb +  HW ))[i];
      float4 e2 = ((const float4*)(eb + 2*HW))[i];
      float4 e3 = ((const float4*)(eb + 3*HW))[i];
      int l0 = (tv.x > 0.5f) ? iv.x : 0;
      int l1 = (tv.y > 0.5f) ? iv.y : 0;
      int l2 = (tv.z > 0.5f) ? iv.z : 0;
      int l3 = (tv.w > 0.5f) ? iv.w : 0;
      pk = (u32)l0 | ((u32)l1<<8) | ((u32)l2<<16) | ((u32)l3<<24);
      const int base = i*4;
#define PROC_A(LV, JJ, KF, E0, E1, E2, E3)                                   \
      if (LV > 0){                                                           \
        u32 key = ~(u32)(base+JJ);                                           \
        u32 lo  = ((volatile u32*)&s_occ[LV])[0];                            \
        if (key > lo) merge_max2(&s_occ[LV], key);                           \
        if (KF > 0.5f){                                                      \
          float* p = mysum + LV*(EDIM*32);                                   \
          p[0] += E0; p[32] += E1; p[64] += E2; p[96] += E3;                 \
          mycnt[LV*32] += 1.f;                                               \
        }                                                                    \
      }
      PROC_A(l0, 0, kv.x, e0.x, e1.x, e2.x, e3.x)
      PROC_A(l1, 1, kv.y, e0.y, e1.y, e2.y, e3.y)
      PROC_A(l2, 2, kv.z, e0.z, e1.z, e2.z, e3.z)
      PROC_A(l3, 3, kv.w, e0.w, e1.w, e2.w, e3.w)
#undef PROC_A
    }
    labpk[it] = pk;
  }
  __syncthreads();

  // block epilogue -> global accumulators
  if (tid < LBL){
    u64 v = s_occ[tid];
    if (v != 0ull){
      merge_max2(&g_occ[b][tid], (u32)(v>>32));
      u32 lo = (u32)v;
      if (lo) merge_max2(&g_occ[b][tid], lo);
    }
  }
  {
    int rw = tid>>5, rl = (tid>>2)&7, rd = tid&3;
    float s = 0.f;
    #pragma unroll
    for (int k = 0; k < 32; k++) s += s_buf[rw][rl][rd][(k+tid)&31];
    if (s != 0.f) atomicAdd(&g_sumk[b][rl][rd], s);
  }
  if (tid < 64){
    int rw = tid>>3, rl = tid&7;
    float c = 0.f;
    #pragma unroll
    for (int k = 0; k < 32; k++) c += s_cnt2[rw][rl][(k+tid)&31];
    if (c != 0.f) atomicAdd(&g_cntk[b][rl], c);
  }
  __syncthreads();

  // ---------------- grid barrier 1 ----------------
  if (tid == 0){
    __threadfence();
    atomicAdd(&g_c1, 1u);
    while (*(volatile u32*)&g_c1 < (u32)NBLK) __nanosleep(64);
    __threadfence();
  }
  __syncthreads();

  // ---------------- per-image small math ----------------
  if (tid < 32){
    int l = tid>>2, d = tid&3;
    float m = 0.f;
    if (l > 0) m = __ldcg(&g_sumk[b][l][d]) / fmaxf(__ldcg(&g_cntk[b][l]), 1.f);
    sm[l][d] = m;
  }
  if (tid < LBL){
    u64 v  = __ldcg(&g_occ[b][tid]);
    u32 f  = ~(u32)(v>>32); if (f  > (u32)(HW-1)) f  = HW-1;
    u32 s2 = ~(u32)v;       if (s2 > (u32)(HW-1)) s2 = HW-1;
    float r0 = (float)(f  / WD), c0 = (float)(f  % WD);
    float r1 = (float)(s2 / WD), c1 = (float)(s2 % WD);
    float dx = r0 - c0, dy = r1 - c1;
    scd[tid] = (tid > 0) ? __expf(__fsqrt_rn(dx*dx + dy*dy) * (0.5f/DIAG)) : 0.f;
    sss[tid] = r0 + c0;
    sst[tid] = r1 + c1;
  }
  __syncthreads();

  if (x == 0 && tid < 64){   // l_dis + l_reg, one block per image
    int ii = tid>>3, jj = tid&7;
    float acc = 0.f;
    if (ii != jj && ii > 0 && jj > 0){
      float sq = 0.f;
      #pragma unroll
      for (int d = 0; d < EDIM; d++){ float dd = sm[ii][d]-sm[jj][d]; sq += dd*dd; }
      float Dn  = __fsqrt_rn(sq);
      float dsp = sss[ii]-sss[jj], dtp = sst[ii]-sst[jj];
      float dp  = __fsqrt_rn(dsp*dsp + dtp*dtp);
      float coef = 1.f - 20.f*__expf(-4.f - 2.5f*dp*(1.f/DIAG));
      float xx = fmaxf(3.f - coef*Dn, 0.f);
      acc = __logf(fmaf(xx,xx,1.f));
    }
    float reg = 0.f;
    if (tid < LBL){
      float sq = 0.f;
      #pragma unroll
      for (int d = 0; d < EDIM; d++) sq += sm[tid][d]*sm[tid][d];
      reg = __logf(__fsqrt_rn(sq) + 1.f);
    }
    red[tid] = acc*(1.f/42.f) + reg*(0.001f/8.f);
  }
  __syncthreads();
  if (x == 0 && tid < 32){
    float v = red[tid] + red[tid+32];
    #pragma unroll
    for (int o = 16; o > 0; o >>= 1) v += __shfl_down_sync(0xffffffffu, v, o);
    if (tid == 0) g_dr[b] = v;
  }

  // ---------------- phase D init (alias s_buf) ----------------
  float* s_val = (float*)s_buf;                       // [w][l][32] -> (w*8+l)*32+lane
  for (int i = tid; i < WARPS*LBL*32; i += NTHR){
    s_val[i] = 0.f; ((float*)s_cnt2)[i] = 0.f;
  }
  __syncthreads();

  float* myval = s_val + w*(LBL*32) + lane;
  // mycnt unchanged

  #pragma unroll
  for (int it = 0; it < ITERS; it++){
    int i = x*NTHR + tid + it*STRIDE;
    if (i < NV4){
      u32 pk = labpk[it];
      float4 e0 = ((const float4*)(eb       ))[i];
      float4 e1 = ((const float4*)(eb +  HW ))[i];
      float4 e2 = ((const float4*)(eb + 2*HW))[i];
      float4 e3 = ((const float4*)(eb + 3*HW))[i];
#define PROC_D(LV, E0, E1, E2, E3)                                           \
      if (LV > 0){                                                           \
        float d0 = E0 - sm[LV][0], d1 = E1 - sm[LV][1];                      \
        float d2 = E2 - sm[LV][2], d3 = E3 - sm[LV][3];                      \
        float sq = d0*d0 + d1*d1 + d2*d2 + d3*d3;                            \
        float xx = fmaxf(scd[LV]*__fsqrt_rn(sq) - 0.5f, 0.f);                \
        myval[LV*32] += __logf(fmaf(xx,xx,1.f));                             \
        mycnt[LV*32] += 1.f;                                                 \
      }
      { int l = (int)(pk      & 0xff); PROC_D(l, e0.x, e1.x, e2.x, e3.x) }
      { int l = (int)((pk>>8 )& 0xff); PROC_D(l, e0.y, e1.y, e2.y, e3.y) }
      { int l = (int)((pk>>16)& 0xff); PROC_D(l, e0.z, e1.z, e2.z, e3.z) }
      { int l = (int)((pk>>24)      ); PROC_D(l, e0.w, e1.w, e2.w, e3.w) }
#undef PROC_D
    }
  }
  __syncthreads();

  if (tid < 64){
    int rw = tid>>3, rl = tid&7;
    float sv = 0.f, sc = 0.f;
    #pragma unroll
    for (int k = 0; k < 32; k++){
      int ln = (k+tid)&31;
      sv += s_val[(rw*LBL + rl)*32 + ln];
      sc += s_cnt2[rw][rl][ln];
    }
    if (rl > 0 && sc != 0.f){
      atomicAdd(&g_agg [b][rl], sv);
      atomicAdd(&g_cntf[b][rl], sc);
    }
  }
  __syncthreads();

  // ---------------- completion + finalize by last block ----------------
  if (tid == 0){
    __threadfence();
    u32 old = atomicAdd(&g_c2, 1u);
    s_last = (old == (u32)(NBLK-1));
  }
  __syncthreads();
  if (!s_last) return;
  __threadfence();

  if (tid < BATCH){
    float s = 0.f;
    #pragma unroll
    for (int l = 1; l < LBL; l++)
      s += __ldcg(&g_agg[tid][l]) / fmaxf(__ldcg(&g_cntf[tid][l]), 1.f);
    red[tid] = s*(1.f/7.f) + __ldcg(&g_dr[tid]);
  }
  __syncthreads();
  if (tid == 0){
    float t = 0.f;
    #pragma unroll
    for (int i = 0; i < BATCH; i++) t += red[i];
    out[0] = t*(1.f/BATCH);
    g_c1 = 0u; g_c2 = 0u;
  }
  // reset scratch to the all-zero rest state for the next graph replay
  if (tid < BATCH*LBL*EDIM) ((float*)g_sumk)[tid] = 0.f;
  if (tid < BATCH*LBL){
    ((u64*)g_occ)[tid]   = 0ull;
    ((float*)g_cntk)[tid] = 0.f;
    ((float*)g_agg )[tid] = 0.f;
    ((float*)g_cntf)[tid] = 0.f;
  }
}

extern "C" void kernel_launch(void* const* d_in, const int* in_sizes, int n_in,
                              void* d_out, int out_size){
  const float* emb   = (const float*)d_in[0];
  const int*   inst  = (const int*)  d_in[1];
  const float* kern  = (const float*)d_in[2];
  const float* tmask = (const float*)d_in[3];
  // d_in[4] = bboxes, unused

  kAll<<<dim3(PB, BATCH), NTHR>>>(emb, inst, kern, tmask, (float*)d_out);
}